// round 1
// baseline (speedup 1.0000x reference)
#include <cuda_runtime.h>

#define MAXN 20000
#define DIN  128
#define DHID 256
#define DDNS 128

// Scratch (no cudaMalloc allowed)
__device__ float g_deg [MAXN];
__device__ float g_dinv[MAXN];
__device__ float g_s   [MAXN];
__device__ float g_t   [MAXN];
__device__ float g_y   [DIN];
__device__ float g_sum_s;

// ---------------------------------------------------------------------------
__global__ void k_init(int n) {
    int i = blockIdx.x * blockDim.x + threadIdx.x;
    if (i < n) g_deg[i] = 1.0f;              // self-loop weight
    if (i < DIN) g_y[i] = 0.0f;
    if (i == 0) g_sum_s = 0.0f;
}

// deg[c] += w  over edges (self-loop already in init)
__global__ void k_deg(const int* __restrict__ col, const float* __restrict__ w, int e) {
    int i = blockIdx.x * blockDim.x + threadIdx.x;
    if (i < e) atomicAdd(&g_deg[col[i]], w[i]);
}

// dinv = rsqrt(deg); s starts at self-loop term dinv^2
__global__ void k_dinv(int n) {
    int i = blockIdx.x * blockDim.x + threadIdx.x;
    if (i < n) {
        float d  = g_deg[i];
        float di = d > 0.0f ? rsqrtf(d) : 0.0f;
        g_dinv[i] = di;
        g_s[i]    = di * di;
    }
}

// s[r] += dinv[r]*w*dinv[c]   (column sums of P)
__global__ void k_s(const int* __restrict__ row, const int* __restrict__ col,
                    const float* __restrict__ w, int e) {
    int i = blockIdx.x * blockDim.x + threadIdx.x;
    if (i < e) {
        int r = row[i], c = col[i];
        atomicAdd(&g_s[r], g_dinv[r] * w[i] * g_dinv[c]);
    }
}

// t self-loop init: t = dinv^2 * s; also reduce sum(s)
__global__ void k_tinit(int n) {
    int i = blockIdx.x * blockDim.x + threadIdx.x;
    float sv = 0.0f;
    if (i < n) {
        float s  = g_s[i];
        float di = g_dinv[i];
        g_t[i] = di * di * s;
        sv = s;
    }
    #pragma unroll
    for (int o = 16; o > 0; o >>= 1) sv += __shfl_down_sync(0xffffffffu, sv, o);
    __shared__ float ws[8];
    int lane = threadIdx.x & 31, wid = threadIdx.x >> 5;
    if (lane == 0) ws[wid] = sv;
    __syncthreads();
    if (wid == 0) {
        sv = (lane < (blockDim.x >> 5)) ? ws[lane] : 0.0f;
        #pragma unroll
        for (int o = 4; o > 0; o >>= 1) sv += __shfl_down_sync(0xffffffffu, sv, o);
        if (lane == 0) atomicAdd(&g_sum_s, sv);
    }
}

// t[r] += dinv[r]*w*dinv[c]*s[c]   (t = P^T s edge part)
__global__ void k_t(const int* __restrict__ row, const int* __restrict__ col,
                    const float* __restrict__ w, int e) {
    int i = blockIdx.x * blockDim.x + threadIdx.x;
    if (i < e) {
        int r = row[i], c = col[i];
        atomicAdd(&g_t[r], g_dinv[r] * w[i] * g_dinv[c] * g_s[c]);
    }
}

// y[d] = sum_n t[n] * X[n,d]   (the only large-memory pass: 10.2 MB)
__global__ void k_y(const float* __restrict__ X, int n) {
    __shared__ float st[128];
    int tid = threadIdx.x;
    int chunk = (n + gridDim.x - 1) / gridDim.x;
    int start = blockIdx.x * chunk;
    int end   = min(n, start + chunk);
    float acc = 0.0f;
    for (int base = start; base < end; base += 128) {
        int m = min(128, end - base);
        if (tid < m) st[tid] = g_t[base + tid];
        __syncthreads();
        for (int k = 0; k < m; k++)
            acc += st[k] * X[(size_t)(base + k) * DIN + tid];
        __syncthreads();
    }
    atomicAdd(&g_y[tid], acc);
}

// Tiny tail: u = y*W1 + sum_s*b1 ; g = u*W2/N + b2 ; z = relu(g*Wd1+bd1) ;
// logits = z*Wd2 + bd2 ; softmax
__global__ void k_final(const float* __restrict__ W1, const float* __restrict__ b1,
                        const float* __restrict__ W2, const float* __restrict__ b2,
                        const float* __restrict__ Wd1, const float* __restrict__ bd1,
                        const float* __restrict__ Wd2, const float* __restrict__ bd2,
                        float* __restrict__ out, int n) {
    __shared__ float sy[DIN];
    __shared__ float su[DHID];
    __shared__ float sg[DHID];
    __shared__ float sz[DDNS];
    __shared__ float sl[2];
    int tid = threadIdx.x;

    if (tid < DIN) sy[tid] = g_y[tid];
    __syncthreads();

    float accu = g_sum_s * b1[tid];
    #pragma unroll 8
    for (int d = 0; d < DIN; d++) accu += sy[d] * W1[d * DHID + tid];
    su[tid] = accu;
    __syncthreads();

    float accg = 0.0f;
    #pragma unroll 8
    for (int k = 0; k < DHID; k++) accg += su[k] * W2[k * DHID + tid];
    sg[tid] = accg / (float)n + b2[tid];
    __syncthreads();

    if (tid < DDNS) {
        float a = bd1[tid];
        #pragma unroll 8
        for (int j = 0; j < DHID; j++) a += sg[j] * Wd1[j * DDNS + tid];
        sz[tid] = a > 0.0f ? a : 0.0f;
    }
    __syncthreads();

    if (tid < 2) {
        float a = bd2[tid];
        for (int i = 0; i < DDNS; i++) a += sz[i] * Wd2[i * 2 + tid];
        sl[tid] = a;
    }
    __syncthreads();

    if (tid == 0) {
        float m  = fmaxf(sl[0], sl[1]);
        float e0 = __expf(sl[0] - m);
        float e1 = __expf(sl[1] - m);
        float inv = 1.0f / (e0 + e1);
        out[0] = e0 * inv;
        out[1] = e1 * inv;
    }
}

// ---------------------------------------------------------------------------
extern "C" void kernel_launch(void* const* d_in, const int* in_sizes, int n_in,
                              void* d_out, int out_size) {
    const float* X   = (const float*)d_in[0];
    const int*   ei  = (const int*)  d_in[1];
    const float* w   = (const float*)d_in[2];
    const float* W1  = (const float*)d_in[3];
    const float* b1  = (const float*)d_in[4];
    const float* W2  = (const float*)d_in[5];
    const float* b2  = (const float*)d_in[6];
    const float* Wd1 = (const float*)d_in[7];
    const float* bd1 = (const float*)d_in[8];
    const float* Wd2 = (const float*)d_in[9];
    const float* bd2 = (const float*)d_in[10];
    float* out = (float*)d_out;

    int n = in_sizes[0] / DIN;        // 20000
    int e = in_sizes[2];              // 640000
    const int* row = ei;
    const int* col = ei + e;

    int nb_n = (n + 255) / 256;
    int nb_e = (e + 255) / 256;

    k_init <<<nb_n, 256>>>(n);
    k_deg  <<<nb_e, 256>>>(col, w, e);
    k_dinv <<<nb_n, 256>>>(n);
    k_s    <<<nb_e, 256>>>(row, col, w, e);
    k_tinit<<<nb_n, 256>>>(n);
    k_t    <<<nb_e, 256>>>(row, col, w, e);
    k_y    <<<160, 128>>>(X, n);
    k_final<<<1, 256>>>(W1, b1, W2, b2, Wd1, bd1, Wd2, bd2, out, n);
}